// round 13
// baseline (speedup 1.0000x reference)
#include <cuda_runtime.h>
#include <stdint.h>

// Coarse key space: 128^3 = 2^21, key = (bx<<14)|(by<<7)|bz.
// Numeric key order == lexicographic row order of jnp.unique. No sort needed.
#define NKEYS   (1 << 21)
#define NWORDS  (NKEYS / 64)     // 32768 u64 presence words = 256 KB (L2-resident)
#define NBLK    128              // scan blocks: 128 x 256 words
#define MAXN    600000

__device__ unsigned long long g_bits[NWORDS];  // presence bitmap
__device__ unsigned           g_wpfx[NWORDS];  // exclusive prefix (rank base) per word
__device__ unsigned           g_rank[NKEYS];   // rank per key; touched ONLY at present keys (no init)
__device__ unsigned           g_bsum[NBLK];    // per-scan-block unique counts (built in k_mark)
__device__ int                g_winner[MAXN * 8]; // last-writer point idx per (rank, offset) slot

__device__ __forceinline__ unsigned pack_key(int cx, int cy, int cz) {
    return ((unsigned)(cx >> 1) << 14) | ((unsigned)(cy >> 1) << 7) | (unsigned)(cz >> 1);
}

// ---------------------------------------------------------------------------
// Fused init: clear bitmap (256 KB) + block sums, winner = -1 (16 MB,
// int4-vectorized), ucoords fill = -1.0f (6 MB). One launch.
__global__ void k_init(float* __restrict__ uc, int n) {
    int i = blockIdx.x * blockDim.x + threadIdx.x;
    if (i < NWORDS) g_bits[i] = 0ull;
    if (i < NBLK)   g_bsum[i] = 0u;
    if (i < n * 2)  ((int4*)g_winner)[i] = make_int4(-1, -1, -1, -1);  // n*8 ints = n*2 int4
    if (i < n * 3)  uc[i] = -1.0f;
}

// Set presence bits; the atomicOr return identifies the FIRST setter of each
// bit, which bumps its scan-block count (exactly one increment per present
// key -> deterministic). This replaces the former k_scan1 reduction kernel.
// Scan-block of key = key >> 14 (256 words = 16384 keys per block).
__global__ void k_mark(const int* __restrict__ coords, int n) {
    int i = blockIdx.x * blockDim.x + threadIdx.x;
    if (i >= n) return;
    int cx = coords[3 * i], cy = coords[3 * i + 1], cz = coords[3 * i + 2];
    unsigned key = pack_key(cx, cy, cz);
    unsigned long long m = 1ull << (key & 63);
    unsigned long long old = atomicOr(&g_bits[key >> 6], m);
    if (!(old & m)) atomicAdd(&g_bsum[key >> 14], 1u);
}

// Per-word exclusive prefix (rank base): block base from g_bsum + intra-block
// scan of word popcounts. One store per word. (Identical to R9's k_wpfx.)
__global__ void k_wpfx() {
    int b = blockIdx.x, t = threadIdx.x;

    __shared__ unsigned red[256];
    red[t] = (t < b) ? g_bsum[t] : 0u;   // b <= 127 < 256
    __syncthreads();
    #pragma unroll
    for (int s = 128; s > 0; s >>= 1) {
        if (t < s) red[t] += red[t + s];
        __syncthreads();
    }
    unsigned blockBase = red[0];
    __syncthreads();

    unsigned c = (unsigned)__popcll(g_bits[b * 256 + t]);
    unsigned lane = t & 31, w = t >> 5;
    unsigned incl = c;
    #pragma unroll
    for (int o = 1; o < 32; o <<= 1) {
        unsigned x = __shfl_up_sync(0xFFFFFFFFu, incl, o);
        if (lane >= o) incl += x;
    }
    __shared__ unsigned wsum[8], woff[8];
    if (lane == 31) wsum[w] = incl;
    __syncthreads();
    if (t == 0) { unsigned a = 0; for (int i = 0; i < 8; i++) { woff[i] = a; a += wsum[i]; } }
    __syncthreads();

    g_wpfx[b * 256 + t] = blockBase + woff[w] + (incl - c);
}

// One thread per KEY (2M threads): fully parallel rank + coord emit.
// rank = wpfx[word] + popc(lower bits). Rank is monotone in key, so
// consecutive present keys write consecutive ucoords rows. (R9-identical.)
__global__ void k_emit(float* __restrict__ ucoords) {
    unsigned k = blockIdx.x * blockDim.x + threadIdx.x;
    if (k >= NKEYS) return;
    unsigned long long word = g_bits[k >> 6];
    unsigned bit = k & 63u;
    if (!((word >> bit) & 1ull)) return;
    unsigned r = g_wpfx[k >> 6] +
                 (unsigned)__popcll(word & ((1ull << bit) - 1ull));
    g_rank[k] = r;
    ucoords[3 * r]     = (float)(k >> 14);
    ucoords[3 * r + 1] = (float)((k >> 7) & 127u);
    ucoords[3 * r + 2] = (float)(k & 127u);
}

// Last-index-wins arbitration per (rank, offset) slot — deterministic match of
// the reference's sequential scatter semantics. (R9-identical.)
__global__ void k_winner(const int* __restrict__ coords, int n) {
    int i = blockIdx.x * blockDim.x + threadIdx.x;
    if (i >= n) return;
    int cx = coords[3 * i], cy = coords[3 * i + 1], cz = coords[3 * i + 2];
    unsigned rank = g_rank[pack_key(cx, cy, cz)];
    int off = ((cx & 1) << 2) | ((cy & 1) << 1) | (cz & 1);
    atomicMax(&g_winner[rank * 8 + off], i);
}

// Row writer: one warp per output row (128 floats = 32 float4). Lane L owns
// float4 #L: slot = L>>2, quarter = L&3; lanes of a slot read a contiguous
// 64B feats segment. Every agg byte written exactly once, streamed with .cs
// (never re-read — keep L2 for the bitmap/rank/winner structures).
__global__ void k_rows(const float* __restrict__ feats,
                       float4* __restrict__ agg4, int n) {
    int warp = (blockIdx.x * blockDim.x + threadIdx.x) >> 5;
    int lane = threadIdx.x & 31;
    if (warp >= n) return;
    int slot = lane >> 2, q = lane & 3;
    int w = g_winner[warp * 8 + slot];
    float4 f = make_float4(0.f, 0.f, 0.f, 0.f);
    if (w >= 0) f = __ldg(&((const float4*)feats)[(size_t)w * 4 + q]);
    __stcs(&agg4[(size_t)warp * 32 + lane], f);
}

// Scalar fallback if agg isn't 16B-aligned (defensive; not expected).
__global__ void k_rows_scalar(const float* __restrict__ feats,
                              float* __restrict__ agg, int n) {
    long long g = (long long)blockIdx.x * blockDim.x + threadIdx.x;
    long long total = (long long)n * 128;
    if (g >= total) return;
    int r = (int)(g >> 7), c = (int)(g & 127);
    int w = g_winner[r * 8 + (c >> 4)];
    agg[g] = (w >= 0) ? feats[(size_t)w * 16 + (c & 15)] : 0.f;
}

// ---------------------------------------------------------------------------
extern "C" void kernel_launch(void* const* d_in, const int* in_sizes, int n_in,
                              void* d_out, int out_size) {
    // metadata order: feats (N*16 f32), coords (N*3 i32). Defensive swap check.
    int fi = 0, ci = 1;
    if (in_sizes[0] < in_sizes[1]) { fi = 1; ci = 0; }
    const float* feats  = (const float*)d_in[fi];
    const int*   coords = (const int*)d_in[ci];
    int n = in_sizes[ci] / 3;

    float* ucoords = (float*)d_out;                     // [n,3]  unique coarse coords AS FLOAT
    float* agg     = (float*)d_out + (size_t)n * 3;     // [n,128] aggregated features

    int initN = n * 3;                                   // covers n*2 int4s, n*3 floats, NWORDS
    if (n * 2 > initN) initN = n * 2;
    if (NWORDS > initN) initN = NWORDS;

    k_init  <<<(initN + 255) / 256, 256>>>(ucoords, n);
    k_mark  <<<(n + 255) / 256, 256>>>(coords, n);
    k_wpfx  <<<NBLK, 256>>>();
    k_emit  <<<NKEYS / 256, 256>>>(ucoords);
    k_winner<<<(n + 255) / 256, 256>>>(coords, n);

    if ((((uintptr_t)agg) & 15) == 0) {
        k_rows<<<(n + 7) / 8, 256>>>(feats, (float4*)agg, n);   // 1 warp/row, 8 rows/block
    } else {
        long long total = (long long)n * 128;
        k_rows_scalar<<<(unsigned)((total + 255) / 256), 256>>>(feats, agg, n);
    }
}

// round 15
// speedup vs baseline: 1.8242x; 1.8242x over previous
#include <cuda_runtime.h>
#include <stdint.h>

// Coarse key space: 128^3 = 2^21, key = (bx<<14)|(by<<7)|bz.
// Numeric key order == lexicographic row order of jnp.unique. No sort needed.
#define NKEYS   (1 << 21)
#define NWORDS  (NKEYS / 64)     // 32768 u64 presence words = 256 KB (L2-resident)
#define NBLK    128              // scan blocks: 128 x 256 threads x 1 word
#define MAXN    600000

__device__ unsigned long long g_bits[NWORDS];  // presence bitmap
__device__ unsigned           g_wpfx[NWORDS];  // exclusive prefix (rank base) per word
__device__ unsigned           g_rank[NKEYS];   // rank per key; touched ONLY at present keys (no init)
__device__ unsigned           g_bsum[NBLK];    // per-scan-block popcount sums
__device__ int                g_winner[MAXN * 8]; // last-writer point idx per (rank, offset) slot

__device__ __forceinline__ unsigned pack_key(int cx, int cy, int cz) {
    return ((unsigned)(cx >> 1) << 14) | ((unsigned)(cy >> 1) << 7) | (unsigned)(cz >> 1);
}

// ---------------------------------------------------------------------------
// Fused init: clear bitmap (256 KB), winner = -1 (int4-vectorized, 16 MB),
// ucoords fill = -1.0f (6 MB). One launch.
__global__ void k_init(float* __restrict__ uc, int n) {
    int i = blockIdx.x * blockDim.x + threadIdx.x;
    if (i < NWORDS) g_bits[i] = 0ull;
    if (i < n * 2)  ((int4*)g_winner)[i] = make_int4(-1, -1, -1, -1);  // n*8 ints = n*2 int4
    if (i < n * 3)  uc[i] = -1.0f;
}

// Set presence bits. 500k atomicOr into a 256 KB L2-resident array.
__global__ void k_mark(const int* __restrict__ coords, int n) {
    int i = blockIdx.x * blockDim.x + threadIdx.x;
    if (i >= n) return;
    int cx = coords[3 * i], cy = coords[3 * i + 1], cz = coords[3 * i + 2];
    unsigned key = pack_key(cx, cy, cz);
    atomicOr(&g_bits[key >> 6], 1ull << (key & 63));
}

// Per-block popcount sums over the bitmap (128 blocks x 256 words).
__global__ void k_scan1() {
    int b = blockIdx.x, t = threadIdx.x;
    unsigned c = (unsigned)__popcll(g_bits[b * 256 + t]);
    #pragma unroll
    for (int o = 16; o > 0; o >>= 1) c += __shfl_down_sync(0xFFFFFFFFu, c, o);
    __shared__ unsigned ws[8];
    if ((t & 31) == 0) ws[t >> 5] = c;
    __syncthreads();
    if (t == 0) {
        unsigned tot = 0;
        #pragma unroll
        for (int w = 0; w < 8; w++) tot += ws[w];
        g_bsum[b] = tot;
    }
}

// Per-word exclusive prefix (rank base): block base from g_bsum + intra-block
// scan of word popcounts. One store per word.
__global__ void k_wpfx() {
    int b = blockIdx.x, t = threadIdx.x;

    __shared__ unsigned red[256];
    red[t] = (t < b) ? g_bsum[t] : 0u;   // b <= 127 < 256
    __syncthreads();
    #pragma unroll
    for (int s = 128; s > 0; s >>= 1) {
        if (t < s) red[t] += red[t + s];
        __syncthreads();
    }
    unsigned blockBase = red[0];
    __syncthreads();

    unsigned c = (unsigned)__popcll(g_bits[b * 256 + t]);
    unsigned lane = t & 31, w = t >> 5;
    unsigned incl = c;
    #pragma unroll
    for (int o = 1; o < 32; o <<= 1) {
        unsigned x = __shfl_up_sync(0xFFFFFFFFu, incl, o);
        if (lane >= o) incl += x;
    }
    __shared__ unsigned wsum[8], woff[8];
    if (lane == 31) wsum[w] = incl;
    __syncthreads();
    if (t == 0) { unsigned a = 0; for (int i = 0; i < 8; i++) { woff[i] = a; a += wsum[i]; } }
    __syncthreads();

    g_wpfx[b * 256 + t] = blockBase + woff[w] + (incl - c);
}

// TWO adjacent keys per thread (1M threads): one word + wpfx load serves both
// keys; two independent rank computations (no dependent chain). Rank is
// monotone in key, so consecutive present keys write consecutive ucoords rows.
__global__ void k_emit(float* __restrict__ ucoords) {
    unsigned p = blockIdx.x * blockDim.x + threadIdx.x;   // pair index
    if (p >= NKEYS / 2) return;
    unsigned k0 = p * 2;
    unsigned long long word = g_bits[k0 >> 6];
    if (word == 0ull) return;
    unsigned base = g_wpfx[k0 >> 6];
    #pragma unroll
    for (int j = 0; j < 2; j++) {
        unsigned k = k0 + j;
        unsigned bit = k & 63u;
        if ((word >> bit) & 1ull) {
            unsigned r = base + (unsigned)__popcll(word & ((1ull << bit) - 1ull));
            g_rank[k] = r;
            ucoords[3 * r]     = (float)(k >> 14);
            ucoords[3 * r + 1] = (float)((k >> 7) & 127u);
            ucoords[3 * r + 2] = (float)(k & 127u);
        }
    }
}

// Last-index-wins arbitration per (rank, offset) slot — deterministic match of
// the reference's sequential scatter semantics.
__global__ void k_winner(const int* __restrict__ coords, int n) {
    int i = blockIdx.x * blockDim.x + threadIdx.x;
    if (i >= n) return;
    int cx = coords[3 * i], cy = coords[3 * i + 1], cz = coords[3 * i + 2];
    unsigned rank = g_rank[pack_key(cx, cy, cz)];
    int off = ((cx & 1) << 2) | ((cy & 1) << 1) | (cz & 1);
    atomicMax(&g_winner[rank * 8 + off], i);
}

// Row writer: one warp per output row (128 floats = 32 float4). Lane L owns
// float4 #L: slot = L>>2, quarter = L&3; lanes of a slot read a contiguous
// 64B feats segment. Every agg byte is written exactly once, streamed with
// .cs (never re-read — keep L2 for the bitmap/rank/winner structures).
__global__ void k_rows(const float* __restrict__ feats,
                       float4* __restrict__ agg4, int n) {
    int warp = (blockIdx.x * blockDim.x + threadIdx.x) >> 5;
    int lane = threadIdx.x & 31;
    if (warp >= n) return;
    int slot = lane >> 2, q = lane & 3;
    int w = g_winner[warp * 8 + slot];
    float4 f = make_float4(0.f, 0.f, 0.f, 0.f);
    if (w >= 0) f = __ldg(&((const float4*)feats)[(size_t)w * 4 + q]);
    __stcs(&agg4[(size_t)warp * 32 + lane], f);
}

// Scalar fallback if agg isn't 16B-aligned (defensive; not expected).
__global__ void k_rows_scalar(const float* __restrict__ feats,
                              float* __restrict__ agg, int n) {
    long long g = (long long)blockIdx.x * blockDim.x + threadIdx.x;
    long long total = (long long)n * 128;
    if (g >= total) return;
    int r = (int)(g >> 7), c = (int)(g & 127);
    int w = g_winner[r * 8 + (c >> 4)];
    agg[g] = (w >= 0) ? feats[(size_t)w * 16 + (c & 15)] : 0.f;
}

// ---------------------------------------------------------------------------
extern "C" void kernel_launch(void* const* d_in, const int* in_sizes, int n_in,
                              void* d_out, int out_size) {
    // metadata order: feats (N*16 f32), coords (N*3 i32). Defensive swap check.
    int fi = 0, ci = 1;
    if (in_sizes[0] < in_sizes[1]) { fi = 1; ci = 0; }
    const float* feats  = (const float*)d_in[fi];
    const int*   coords = (const int*)d_in[ci];
    int n = in_sizes[ci] / 3;

    float* ucoords = (float*)d_out;                     // [n,3]  unique coarse coords AS FLOAT
    float* agg     = (float*)d_out + (size_t)n * 3;     // [n,128] aggregated features

    int initN = n * 3;                                   // covers n*2 int4s, n*3 floats, NWORDS
    if (n * 2 > initN) initN = n * 2;
    if (NWORDS > initN) initN = NWORDS;

    k_init  <<<(initN + 255) / 256, 256>>>(ucoords, n);
    k_mark  <<<(n + 255) / 256, 256>>>(coords, n);
    k_scan1 <<<NBLK, 256>>>();
    k_wpfx  <<<NBLK, 256>>>();
    k_emit  <<<(NKEYS / 2) / 256, 256>>>(ucoords);
    k_winner<<<(n + 255) / 256, 256>>>(coords, n);

    if ((((uintptr_t)agg) & 15) == 0) {
        k_rows<<<(n + 7) / 8, 256>>>(feats, (float4*)agg, n);   // 1 warp/row, 8 rows/block
    } else {
        long long total = (long long)n * 128;
        k_rows_scalar<<<(unsigned)((total + 255) / 256), 256>>>(feats, agg, n);
    }
}